// round 1
// baseline (speedup 1.0000x reference)
#include <cuda_runtime.h>

// GRUAdder: B ~ 1M, T=4, I=2, H=16.
// Outputs (concatenated, float32): hidden_table [B,4,16], sum_logits [B,4],
// carry_logit [B,1], output_logits [B,5]  => 74 floats per batch row.

#define TT 4
#define II 2
#define HH 16
#define G  48   // 3*H

__device__ __forceinline__ float fsig(float x) {
    // sigmoid(x) = 1 / (1 + exp(-x)), exp via ex2.approx (rel err ~2^-22)
    float e, r;
    asm("ex2.approx.f32 %0, %1;" : "=f"(e) : "f"(-1.4426950408889634f * x));
    asm("rcp.approx.f32 %0, %1;" : "=f"(r) : "f"(1.0f + e));
    return r;
}

__device__ __forceinline__ float ftanh_fast(float x) {
    // tanh(x) = 2/(1+exp(-2x)) - 1
    float e, r;
    asm("ex2.approx.f32 %0, %1;" : "=f"(e) : "f"(-2.8853900817779268f * x));
    asm("rcp.approx.f32 %0, %1;" : "=f"(r) : "f"(1.0f + e));
    return 2.0f * r - 1.0f;
}

__global__ void gru_adder_kernel(
    const float* __restrict__ x,        // [B, 4, 2]
    const float* __restrict__ w_ih,     // [48, 2]
    const float* __restrict__ w_hh,     // [48, 16]
    const float* __restrict__ b_ih,     // [48]
    const float* __restrict__ b_hh,     // [48]
    const float* __restrict__ w_sum,    // [1, 16]
    const float* __restrict__ b_sum,    // [1]
    const float* __restrict__ w_carry,  // [1, 16]
    const float* __restrict__ b_carry,  // [1]
    float* __restrict__ hid,            // [B, 4, 16] or null
    float* __restrict__ sumo,           // [B, 4] or null
    float* __restrict__ carryo,         // [B] or null
    float* __restrict__ olog,           // [B, 5] or null
    int B)
{
    __shared__ float s_whhT[HH][G];   // transposed: [k][j], row = 192B (16B aligned)
    __shared__ float s_wih0[G], s_wih1[G];
    __shared__ float s_brz[32];       // b_ih + b_hh for r,z gates (j < 32)
    __shared__ float s_bin[HH];       // b_ih for n gate
    __shared__ float s_bhn[HH];       // b_hh for n gate
    __shared__ float s_wsum[HH], s_wcar[HH];
    __shared__ float s_bs, s_bc;

    for (int idx = threadIdx.x; idx < G * HH; idx += blockDim.x) {
        int j = idx / HH, k = idx % HH;
        s_whhT[k][j] = w_hh[idx];
    }
    for (int j = threadIdx.x; j < G; j += blockDim.x) {
        s_wih0[j] = w_ih[j * II + 0];
        s_wih1[j] = w_ih[j * II + 1];
        if (j < 32) {
            s_brz[j] = b_ih[j] + b_hh[j];
        } else {
            s_bin[j - 32] = b_ih[j];
            s_bhn[j - 32] = b_hh[j];
        }
        if (j < HH) { s_wsum[j] = w_sum[j]; s_wcar[j] = w_carry[j]; }
        if (j == 0) { s_bs = b_sum[0]; s_bc = b_carry[0]; }
    }
    __syncthreads();

    int b = blockIdx.x * blockDim.x + threadIdx.x;
    if (b >= B) return;

    // x for this row: 8 contiguous floats, 32B-aligned -> 2x LDG.128
    float4 xv0 = reinterpret_cast<const float4*>(x)[(size_t)b * 2 + 0];
    float4 xv1 = reinterpret_cast<const float4*>(x)[(size_t)b * 2 + 1];
    float xs[8] = {xv0.x, xv0.y, xv0.z, xv0.w, xv1.x, xv1.y, xv1.z, xv1.w};

    float h[HH];
    #pragma unroll
    for (int j = 0; j < HH; j++) h[j] = 0.0f;

    float sums[TT];

    #pragma unroll
    for (int t = 0; t < TT; t++) {
        const float x0 = xs[t * 2 + 0];
        const float x1 = xs[t * 2 + 1];

        float acc[G];   // j<32: full r/z pre-activation; j>=32: h_n part only
        float gin[HH];  // i_n part for n gate

        #pragma unroll
        for (int j = 0; j < 32; j++)
            acc[j] = s_brz[j] + s_wih0[j] * x0 + s_wih1[j] * x1;
        #pragma unroll
        for (int j = 0; j < HH; j++) {
            gin[j] = s_bin[j] + s_wih0[32 + j] * x0 + s_wih1[32 + j] * x1;
            acc[32 + j] = s_bhn[j];
        }

        // acc[j] += sum_k w_hh[j][k] * h[k]   (warp-uniform LDS.128 broadcast)
        #pragma unroll
        for (int k = 0; k < HH; k++) {
            const float hk = h[k];
            const float4* wrow = reinterpret_cast<const float4*>(&s_whhT[k][0]);
            #pragma unroll
            for (int j4 = 0; j4 < G / 4; j4++) {
                float4 w = wrow[j4];
                acc[j4 * 4 + 0] += w.x * hk;
                acc[j4 * 4 + 1] += w.y * hk;
                acc[j4 * 4 + 2] += w.z * hk;
                acc[j4 * 4 + 3] += w.w * hk;
            }
        }

        float s = s_bs;
        #pragma unroll
        for (int j = 0; j < HH; j++) {
            float r = fsig(acc[j]);
            float z = fsig(acc[16 + j]);
            float n = ftanh_fast(gin[j] + r * acc[32 + j]);
            float hn = n + z * (h[j] - n);   // (1-z)*n + z*h
            h[j] = hn;
            s += hn * s_wsum[j];
        }
        sums[t] = s;

        if (hid) {
            float4* hp = reinterpret_cast<float4*>(hid + (size_t)b * (TT * HH) + t * HH);
            hp[0] = make_float4(h[0],  h[1],  h[2],  h[3]);
            hp[1] = make_float4(h[4],  h[5],  h[6],  h[7]);
            hp[2] = make_float4(h[8],  h[9],  h[10], h[11]);
            hp[3] = make_float4(h[12], h[13], h[14], h[15]);
        }
    }

    float c = s_bc;
    #pragma unroll
    for (int j = 0; j < HH; j++) c += h[j] * s_wcar[j];

    if (sumo)
        reinterpret_cast<float4*>(sumo)[b] = make_float4(sums[0], sums[1], sums[2], sums[3]);
    if (carryo)
        carryo[b] = c;
    if (olog) {
        float* o = olog + (size_t)b * 5;
        o[0] = sums[0]; o[1] = sums[1]; o[2] = sums[2]; o[3] = sums[3]; o[4] = c;
    }
}

extern "C" void kernel_launch(void* const* d_in, const int* in_sizes, int n_in,
                              void* d_out, int out_size) {
    const float* x       = (const float*)d_in[0];
    const float* w_ih    = (const float*)d_in[1];
    const float* w_hh    = (const float*)d_in[2];
    const float* b_ih    = (const float*)d_in[3];
    const float* b_hh    = (const float*)d_in[4];
    const float* w_sum   = (const float*)d_in[5];
    const float* b_sum   = (const float*)d_in[6];
    const float* w_carry = (const float*)d_in[7];
    const float* b_carry = (const float*)d_in[8];

    long long B = (long long)in_sizes[0] / (TT * II);
    float* out = (float*)d_out;
    long long os = (long long)out_size;

    // Defensive output-layout resolution: reference returns
    // (hidden_table, sum_logits, carry_logit, output_logits); assume the
    // harness concatenates flattened outputs. Fall back to partial layouts.
    float *hid = nullptr, *sum = nullptr, *car = nullptr, *olog = nullptr;
    if (os >= B * 74) {
        hid = out; sum = out + B * 64; car = out + B * 68; olog = out + B * 69;
    } else if (os >= B * 64) {
        hid = out;
    } else if (os >= B * 5) {
        olog = out;
    } else if (os >= B * 4) {
        sum = out;
    } else {
        car = out;
    }

    const int threads = 256;
    int grid = (int)((B + threads - 1) / threads);
    gru_adder_kernel<<<grid, threads>>>(x, w_ih, w_hh, b_ih, b_hh,
                                        w_sum, b_sum, w_carry, b_carry,
                                        hid, sum, car, olog, (int)B);
}